// round 8
// baseline (speedup 1.0000x reference)
#include <cuda_runtime.h>
#include <cstdint>

// ---------------------------------------------------------------------------
// TwoDRNN: h = h1@U1 + h2@U2 ; GRU(h, x) -> new_h (written twice)
// B=262144, DH=128, DM=4.
// One CTA = 128 batch rows, 8 warps, 256 threads, fully fused.
// TF32 mma.sync (m16n8k8), cvt.rna rounding.
// Warp tile m32 x n64: B fragments reused across 2 m-subtiles (-33% LDS).
// ---------------------------------------------------------------------------

#define DHID 128
#define DMIN 4
#define TILE_M 128

constexpr int LDA = 132;   // stride (floats) for A-style tiles (sA, sH)
constexpr int LDW = 136;   // stride (floats) for weight tiles (sW)

// smem layout (floats)
constexpr int OFF_A   = 0;
constexpr int OFF_H   = OFF_A  + TILE_M * LDA;          // 16896
constexpr int OFF_W   = OFF_H  + TILE_M * LDA;          // 33792
constexpr int OFF_X   = OFF_W  + DHID * LDW;            // 51200
constexpr int OFF_WI  = OFF_X  + TILE_M * DMIN;         // 51712
constexpr int OFF_BI  = OFF_WI + DMIN * 3 * DHID;       // 53248
constexpr int OFF_BHN = OFF_BI + 3 * DHID;              // 53632
constexpr int SMEM_FLOATS = OFF_BHN + DHID;             // 53760
constexpr int SMEM_BYTES  = SMEM_FLOATS * 4;            // 215040 B

__device__ __forceinline__ unsigned f2tf(float x) {
    unsigned u;
    asm("cvt.rna.tf32.f32 %0, %1;" : "=r"(u) : "f"(x));
    return u;
}

__device__ __forceinline__ void mma8(float* d, unsigned a0, unsigned a1,
                                     unsigned a2, unsigned a3,
                                     unsigned b0, unsigned b1) {
    asm volatile(
        "mma.sync.aligned.m16n8k8.row.col.f32.tf32.tf32.f32 "
        "{%0,%1,%2,%3}, {%4,%5,%6,%7}, {%8,%9}, {%0,%1,%2,%3};"
        : "+f"(d[0]), "+f"(d[1]), "+f"(d[2]), "+f"(d[3])
        : "r"(a0), "r"(a1), "r"(a2), "r"(a3), "r"(b0), "r"(b1));
}

__device__ __forceinline__ float sigmoidf_(float v) {
    return 1.0f / (1.0f + __expf(-v));
}

__device__ __forceinline__ float tanhf_(float v) {
    float c = fminf(fmaxf(v, -15.0f), 15.0f);
    float e = __expf(2.0f * c);
    return (e - 1.0f) / (e + 1.0f);
}

// Copy a 128x128 fp32 tile global->smem, optionally rounding to tf32.
__device__ __forceinline__ void load_tile(const float* __restrict__ g,
                                          int gstride, float* s, int lds,
                                          int tid, bool round_tf32) {
#pragma unroll
    for (int it = 0; it < 16; ++it) {
        int i  = it * 256 + tid;        // 0..4095 float4 slots
        int r  = i >> 5;                // 32 float4 per row
        int c4 = (i & 31) << 2;
        float4 v = *reinterpret_cast<const float4*>(g + (long)r * gstride + c4);
        if (round_tf32) {
            v.x = __uint_as_float(f2tf(v.x));
            v.y = __uint_as_float(f2tf(v.y));
            v.z = __uint_as_float(f2tf(v.z));
            v.w = __uint_as_float(f2tf(v.w));
        }
        *reinterpret_cast<float4*>(s + r * lds + c4) = v;
    }
}

// Warp-tile GEMM-accumulate: acc += A[mBase:mBase+32, :128] @ W[:, nBase:nBase+64].
// acc layout: acc[(mt*8 + t)*4 + q], mt in 0..1 (m16 subtile), t in 0..7 (n8 tile).
__device__ __forceinline__ void gemm_tile(const float* sAop, int lda,
                                          const float* sWop, float acc[64],
                                          int mBase, int nBase, int g, int ctg) {
#pragma unroll
    for (int ks = 0; ks < 16; ++ks) {
        const int k0 = ks * 8;
        // A fragments for both m16 subtiles
        unsigned a[2][4];
#pragma unroll
        for (int mt = 0; mt < 2; ++mt) {
            const float* ar0 = sAop + (mBase + mt * 16 + g) * lda + k0;
            const float* ar1 = ar0 + 8 * lda;
            a[mt][0] = f2tf(ar0[ctg]);
            a[mt][1] = f2tf(ar1[ctg]);
            a[mt][2] = f2tf(ar0[ctg + 4]);
            a[mt][3] = f2tf(ar1[ctg + 4]);
        }
        const float* bk0 = sWop + (k0 + ctg) * LDW + nBase + g;
        const float* bk1 = bk0 + 4 * LDW;
#pragma unroll
        for (int t = 0; t < 8; ++t) {
            unsigned b0 = __float_as_uint(bk0[t * 8]);
            unsigned b1 = __float_as_uint(bk1[t * 8]);
            mma8(acc + (0 * 8 + t) * 4, a[0][0], a[0][1], a[0][2], a[0][3], b0, b1);
            mma8(acc + (1 * 8 + t) * 4, a[1][0], a[1][1], a[1][2], a[1][3], b0, b1);
        }
    }
}

__global__ __launch_bounds__(256, 1)
void twodrnn_kernel(const float* __restrict__ x,
                    const float* __restrict__ h1,
                    const float* __restrict__ h2,
                    const float* __restrict__ U1,
                    const float* __restrict__ U2,
                    const float* __restrict__ Wi,
                    const float* __restrict__ bi,
                    const float* __restrict__ Whrz,
                    const float* __restrict__ Whn,
                    const float* __restrict__ bhn,
                    float* __restrict__ out,
                    long dup_off /* 0 = no duplicate second half */) {
    extern __shared__ float sm[];
    float* sA   = sm + OFF_A;
    float* sH   = sm + OFF_H;
    float* sW   = sm + OFF_W;
    float* sX   = sm + OFF_X;
    float* sWi  = sm + OFF_WI;
    float* sBi  = sm + OFF_BI;
    float* sBhn = sm + OFF_BHN;

    const int tid  = threadIdx.x;
    const int warp = tid >> 5;
    const int lane = tid & 31;
    const int g    = lane >> 2;   // row group within fragment
    const int ctg  = lane & 3;    // k/col subgroup within fragment
    const int mBase = (warp & 3) * 32;   // warp covers rows mBase..mBase+31
    const int nBase = (warp >> 2) * 64;  // warp covers cols nBase..nBase+63
    const long rowBase = (long)blockIdx.x * TILE_M;

    // small parameters
    for (int i = tid; i < DMIN * 3 * DHID; i += 256) sWi[i] = Wi[i];
    for (int i = tid; i < 3 * DHID; i += 256)        sBi[i] = bi[i];
    for (int i = tid; i < DHID; i += 256)            sBhn[i] = bhn[i];
    for (int i = tid; i < TILE_M * DMIN; i += 256)   sX[i] = x[rowBase * DMIN + i];

    float acc[64];
#pragma unroll
    for (int i = 0; i < 64; ++i) acc[i] = 0.0f;

    // ---------------- stage 1: h = h1@U1 + h2@U2 ----------------
    load_tile(h1 + rowBase * DHID, DHID, sA, LDA, tid, false);
    load_tile(U1, DHID, sW, LDW, tid, true);
    __syncthreads();
    gemm_tile(sA, LDA, sW, acc, mBase, nBase, g, ctg);
    __syncthreads();
    load_tile(h2 + rowBase * DHID, DHID, sA, LDA, tid, false);
    load_tile(U2, DHID, sW, LDW, tid, true);
    __syncthreads();
    gemm_tile(sA, LDA, sW, acc, mBase, nBase, g, ctg);

    // store h -> sH (fp32, full precision for epilogue + stage-2 A operand)
#pragma unroll
    for (int mt = 0; mt < 2; ++mt) {
#pragma unroll
        for (int t = 0; t < 8; ++t) {
            const float* a4 = acc + (mt * 8 + t) * 4;
            int r0 = mBase + mt * 16 + g;
            int c  = nBase + t * 8 + 2 * ctg;
            *reinterpret_cast<float2*>(&sH[r0 * LDA + c]) =
                make_float2(a4[0], a4[1]);
            *reinterpret_cast<float2*>(&sH[(r0 + 8) * LDA + c]) =
                make_float2(a4[2], a4[3]);
        }
    }

    // ---------------- stage 2: chunks hr -> hn -> hz ----------------
    // chunk 0: Whrz[:, 0:128]   -> r = sigmoid(ir + hr), store r in sA
    // chunk 1: Whn              -> n = tanh(i_n + r*(hn + bhn)), store n in sA
    // chunk 2: Whrz[:, 128:256] -> z = sigmoid(iz + hz); new_h -> sH
#pragma unroll
    for (int c = 0; c < 3; ++c) {
        __syncthreads();   // sW consumers done; sH stores (c==0) visible
        if (c == 0)      load_tile(Whrz,       2 * DHID, sW, LDW, tid, true);
        else if (c == 1) load_tile(Whn,        DHID,     sW, LDW, tid, true);
        else             load_tile(Whrz + 128, 2 * DHID, sW, LDW, tid, true);
        __syncthreads();
#pragma unroll
        for (int i = 0; i < 64; ++i) acc[i] = 0.0f;
        gemm_tile(sH, LDA, sW, acc, mBase, nBase, g, ctg);

#pragma unroll
        for (int mt = 0; mt < 2; ++mt) {
#pragma unroll
            for (int t = 0; t < 8; ++t) {
#pragma unroll
                for (int q = 0; q < 4; ++q) {
                    const int rr = mBase + mt * 16 + g + ((q >= 2) ? 8 : 0);
                    const int cc = nBase + t * 8 + 2 * ctg + (q & 1);
                    const float v = acc[(mt * 8 + t) * 4 + q];
                    const float x0 = sX[rr * 4 + 0];
                    const float x1 = sX[rr * 4 + 1];
                    const float x2 = sX[rr * 4 + 2];
                    const float x3 = sX[rr * 4 + 3];
                    if (c == 0) {
                        const int j = cc;           // ir block
                        float ip = sBi[j]
                                 + x0 * sWi[0 * 384 + j] + x1 * sWi[1 * 384 + j]
                                 + x2 * sWi[2 * 384 + j] + x3 * sWi[3 * 384 + j];
                        sA[rr * LDA + cc] = sigmoidf_(ip + v);          // r
                    } else if (c == 1) {
                        const int j = cc + 256;     // i_n block
                        float ip = sBi[j]
                                 + x0 * sWi[0 * 384 + j] + x1 * sWi[1 * 384 + j]
                                 + x2 * sWi[2 * 384 + j] + x3 * sWi[3 * 384 + j];
                        float r = sA[rr * LDA + cc];
                        sA[rr * LDA + cc] = tanhf_(ip + r * (v + sBhn[cc])); // n
                    } else {
                        const int j = cc + 128;     // iz block
                        float ip = sBi[j]
                                 + x0 * sWi[0 * 384 + j] + x1 * sWi[1 * 384 + j]
                                 + x2 * sWi[2 * 384 + j] + x3 * sWi[3 * 384 + j];
                        float z = sigmoidf_(ip + v);
                        float hv = sH[rr * LDA + cc];
                        float n  = sA[rr * LDA + cc];
                        sH[rr * LDA + cc] = (1.0f - z) * n + z * hv;    // new_h
                    }
                }
            }
        }
    }
    __syncthreads();

    // coalesced writeback (twice if the output is the (new_h, new_h) tuple)
    float* o0 = out + rowBase * DHID;
#pragma unroll
    for (int it = 0; it < 16; ++it) {
        int i  = it * 256 + tid;
        int r  = i >> 5;
        int c4 = (i & 31) << 2;
        float4 v = *reinterpret_cast<const float4*>(sH + r * LDA + c4);
        *reinterpret_cast<float4*>(o0 + (long)r * DHID + c4) = v;
        if (dup_off)
            *reinterpret_cast<float4*>(o0 + dup_off + (long)r * DHID + c4) = v;
    }
}

extern "C" void kernel_launch(void* const* d_in, const int* in_sizes, int n_in,
                              void* d_out, int out_size) {
    // Idempotent, capture-safe, unconditional (no static guards per harness rules).
    cudaFuncSetAttribute(twodrnn_kernel,
                         cudaFuncAttributeMaxDynamicSharedMemorySize,
                         SMEM_BYTES);

    const float* x    = (const float*)d_in[0];
    const float* h1   = (const float*)d_in[1];
    const float* h2   = (const float*)d_in[2];
    const float* U1   = (const float*)d_in[3];
    const float* U2   = (const float*)d_in[4];
    const float* Wi   = (const float*)d_in[5];
    const float* bi   = (const float*)d_in[6];
    const float* Whrz = (const float*)d_in[7];
    const float* Whn  = (const float*)d_in[8];
    const float* bhn  = (const float*)d_in[9];

    const int Brows = in_sizes[1] / DHID;            // 262144
    const int grid  = Brows / TILE_M;                // 2048
    const long base = (long)Brows * DHID;
    const long dup_off = ((long)out_size >= 2 * base) ? base : 0;

    twodrnn_kernel<<<grid, 256, SMEM_BYTES>>>(
        x, h1, h2, U1, U2, Wi, bi, Whrz, Whn, bhn, (float*)d_out, dup_off);
}

// round 9
// speedup vs baseline: 1.0191x; 1.0191x over previous
#include <cuda_runtime.h>
#include <cstdint>

// ---------------------------------------------------------------------------
// TwoDRNN: h = h1@U1 + h2@U2 ; GRU(h, x) -> new_h (written twice)
// B=262144, DH=128, DM=4.  One CTA = 128 rows, 8 warps, fully fused.
// TF32 mma.sync m16n8k8; warp tile m32 x n64.
// R8: software-pipelined (register prefetch of next tile during gemm),
//     gates r/n kept in registers, weights rounded once at STS.
// ---------------------------------------------------------------------------

#define DHID 128
#define DMIN 4
#define TILE_M 128

constexpr int LDA = 132;   // A/H tile stride (banks: 4g+ctg conflict-free)
constexpr int LDW = 136;   // W tile stride  (banks: 8ctg+g conflict-free)

constexpr int OFF_AH  = 0;
constexpr int OFF_W0  = OFF_AH + TILE_M * LDA;          // 16896
constexpr int OFF_W1  = OFF_W0 + DHID * LDW;            // 34304
constexpr int OFF_X   = OFF_W1 + DHID * LDW;            // 51712
constexpr int OFF_WI  = OFF_X  + TILE_M * DMIN;         // 52224
constexpr int OFF_BI  = OFF_WI + DMIN * 3 * DHID;       // 53760
constexpr int OFF_BHN = OFF_BI + 3 * DHID;              // 54144
constexpr int SMEM_FLOATS = OFF_BHN + DHID;             // 54272
constexpr int SMEM_BYTES  = SMEM_FLOATS * 4;            // 217088 B

__device__ __forceinline__ unsigned f2tf(float x) {
    unsigned u;
    asm("cvt.rna.tf32.f32 %0, %1;" : "=r"(u) : "f"(x));
    return u;
}

__device__ __forceinline__ void mma8(float* d, unsigned a0, unsigned a1,
                                     unsigned a2, unsigned a3,
                                     unsigned b0, unsigned b1) {
    asm volatile(
        "mma.sync.aligned.m16n8k8.row.col.f32.tf32.tf32.f32 "
        "{%0,%1,%2,%3}, {%4,%5,%6,%7}, {%8,%9}, {%0,%1,%2,%3};"
        : "+f"(d[0]), "+f"(d[1]), "+f"(d[2]), "+f"(d[3])
        : "r"(a0), "r"(a1), "r"(a2), "r"(a3), "r"(b0), "r"(b1));
}

__device__ __forceinline__ float sigmoidf_(float v) {
    return 1.0f / (1.0f + __expf(-v));
}

__device__ __forceinline__ float tanhf_(float v) {
    float c = fminf(fmaxf(v, -15.0f), 15.0f);
    float e = __expf(2.0f * c);
    return (e - 1.0f) / (e + 1.0f);
}

// Prefetch a 128x128 fp32 tile into registers (16 float4 / thread).
__device__ __forceinline__ void ldg_tile(const float* __restrict__ g,
                                         int gstride, float4 r[16], int tid) {
#pragma unroll
    for (int it = 0; it < 16; ++it) {
        int i  = it * 256 + tid;
        int rw = i >> 5;
        int c4 = (i & 31) << 2;
        r[it] = *reinterpret_cast<const float4*>(g + (long)rw * gstride + c4);
    }
}

// Commit prefetched tile to smem, optionally rounding to tf32 (rna).
template <bool ROUND>
__device__ __forceinline__ void sts_tile(const float4 r[16], float* s,
                                         int lds, int tid) {
#pragma unroll
    for (int it = 0; it < 16; ++it) {
        int i  = it * 256 + tid;
        int rw = i >> 5;
        int c4 = (i & 31) << 2;
        float4 v = r[it];
        if (ROUND) {
            v.x = __uint_as_float(f2tf(v.x));
            v.y = __uint_as_float(f2tf(v.y));
            v.z = __uint_as_float(f2tf(v.z));
            v.w = __uint_as_float(f2tf(v.w));
        }
        *reinterpret_cast<float4*>(s + rw * lds + c4) = v;
    }
}

// Warp-tile GEMM-accumulate: acc += A[mBase:+32, :128] @ W[:, nBase:+64].
// acc[(mt*8+t)*4+q].  CVTA: round A fragments (A stored fp32, e.g. h).
template <bool CVTA>
__device__ __forceinline__ void gemm_tile(const float* sAop, const float* sWop,
                                          float acc[64], int mBase, int nBase,
                                          int g, int ctg) {
#pragma unroll
    for (int ks = 0; ks < 16; ++ks) {
        const int k0 = ks * 8;
        unsigned a[2][4];
#pragma unroll
        for (int mt = 0; mt < 2; ++mt) {
            const float* ar0 = sAop + (mBase + mt * 16 + g) * LDA + k0;
            const float* ar1 = ar0 + 8 * LDA;
            if (CVTA) {
                a[mt][0] = f2tf(ar0[ctg]);
                a[mt][1] = f2tf(ar1[ctg]);
                a[mt][2] = f2tf(ar0[ctg + 4]);
                a[mt][3] = f2tf(ar1[ctg + 4]);
            } else {
                a[mt][0] = __float_as_uint(ar0[ctg]);
                a[mt][1] = __float_as_uint(ar1[ctg]);
                a[mt][2] = __float_as_uint(ar0[ctg + 4]);
                a[mt][3] = __float_as_uint(ar1[ctg + 4]);
            }
        }
        const float* bk0 = sWop + (k0 + ctg) * LDW + nBase + g;
        const float* bk1 = bk0 + 4 * LDW;
#pragma unroll
        for (int t = 0; t < 8; ++t) {
            unsigned b0 = __float_as_uint(bk0[t * 8]);
            unsigned b1 = __float_as_uint(bk1[t * 8]);
            mma8(acc + (0 * 8 + t) * 4, a[0][0], a[0][1], a[0][2], a[0][3], b0, b1);
            mma8(acc + (1 * 8 + t) * 4, a[1][0], a[1][1], a[1][2], a[1][3], b0, b1);
        }
    }
}

// GRU epilogue for chunk CH (0: r, 1: n, 2: z + blend).
template <int CH>
__device__ __forceinline__ void epilogue(const float acc[64], float gate[64],
                                         float* sAH, const float* sX,
                                         const float* sWi, const float* sBi,
                                         const float* sBhn,
                                         int mBase, int nBase, int g, int ctg) {
    float xv[4][4];
#pragma unroll
    for (int mt = 0; mt < 2; ++mt)
#pragma unroll
        for (int qh = 0; qh < 2; ++qh) {
            int rr = mBase + mt * 16 + g + qh * 8;
#pragma unroll
            for (int k = 0; k < 4; ++k) xv[mt * 2 + qh][k] = sX[rr * 4 + k];
        }
#pragma unroll
    for (int t = 0; t < 8; ++t) {
#pragma unroll
        for (int ql = 0; ql < 2; ++ql) {
            const int cc = nBase + t * 8 + 2 * ctg + ql;
            const int j  = cc + (CH == 0 ? 0 : (CH == 1 ? 256 : 128));
            const float w0 = sWi[0 * 384 + j];
            const float w1 = sWi[1 * 384 + j];
            const float w2 = sWi[2 * 384 + j];
            const float w3 = sWi[3 * 384 + j];
            const float bb = sBi[j];
            const float bh = (CH == 1) ? sBhn[cc] : 0.0f;
#pragma unroll
            for (int mt = 0; mt < 2; ++mt)
#pragma unroll
                for (int qh = 0; qh < 2; ++qh) {
                    const int idx = (mt * 8 + t) * 4 + qh * 2 + ql;
                    const float* xp = xv[mt * 2 + qh];
                    float ip = bb + xp[0] * w0 + xp[1] * w1
                                  + xp[2] * w2 + xp[3] * w3;
                    const float v = acc[idx];
                    if (CH == 0) {
                        gate[idx] = sigmoidf_(ip + v);             // r
                    } else if (CH == 1) {
                        gate[idx] = tanhf_(ip + gate[idx] * (v + bh)); // n
                    } else {
                        const int rr = mBase + mt * 16 + g + qh * 8;
                        float z  = sigmoidf_(ip + v);
                        float hv = sAH[rr * LDA + cc];
                        sAH[rr * LDA + cc] = (1.0f - z) * gate[idx] + z * hv;
                    }
                }
        }
    }
}

__global__ __launch_bounds__(256, 1)
void twodrnn_kernel(const float* __restrict__ x,
                    const float* __restrict__ h1,
                    const float* __restrict__ h2,
                    const float* __restrict__ U1,
                    const float* __restrict__ U2,
                    const float* __restrict__ Wi,
                    const float* __restrict__ bi,
                    const float* __restrict__ Whrz,
                    const float* __restrict__ Whn,
                    const float* __restrict__ bhn,
                    float* __restrict__ out,
                    long dup_off) {
    extern __shared__ float sm[];
    float* sAH  = sm + OFF_AH;
    float* sW0  = sm + OFF_W0;
    float* sW1  = sm + OFF_W1;
    float* sX   = sm + OFF_X;
    float* sWi  = sm + OFF_WI;
    float* sBi  = sm + OFF_BI;
    float* sBhn = sm + OFF_BHN;

    const int tid  = threadIdx.x;
    const int warp = tid >> 5;
    const int lane = tid & 31;
    const int g    = lane >> 2;
    const int ctg  = lane & 3;
    const int mBase = (warp & 3) * 32;
    const int nBase = (warp >> 2) * 64;
    const long rowBase = (long)blockIdx.x * TILE_M;

    float4 rA[16], rW[16];

    // phase -1: initial loads (h1, U1) + small params
    ldg_tile(h1 + rowBase * DHID, DHID, rA, tid);
    ldg_tile(U1, DHID, rW, tid);
    for (int i = tid; i < DMIN * 3 * DHID; i += 256) sWi[i] = Wi[i];
    for (int i = tid; i < 3 * DHID; i += 256)        sBi[i] = bi[i];
    for (int i = tid; i < DHID; i += 256)            sBhn[i] = bhn[i];
    for (int i = tid; i < TILE_M * DMIN; i += 256)   sX[i] = x[rowBase * DMIN + i];
    sts_tile<true>(rA, sAH, LDA, tid);     // h1 rounded to tf32 (MMA-only use)
    sts_tile<true>(rW, sW0, LDW, tid);
    __syncthreads();

    float acc[64];
#pragma unroll
    for (int i = 0; i < 64; ++i) acc[i] = 0.0f;

    // gemm1: h1@U1, prefetch h2+U2 under it
    ldg_tile(h2 + rowBase * DHID, DHID, rA, tid);
    ldg_tile(U2, DHID, rW, tid);
    gemm_tile<false>(sAH, sW0, acc, mBase, nBase, g, ctg);
    __syncthreads();
    sts_tile<true>(rA, sAH, LDA, tid);
    sts_tile<true>(rW, sW1, LDW, tid);
    __syncthreads();

    // gemm2: h2@U2, prefetch Whrz[:, 0:128] under it
    ldg_tile(Whrz, 2 * DHID, rW, tid);
    gemm_tile<false>(sAH, sW1, acc, mBase, nBase, g, ctg);
    __syncthreads();

    // stage h (full fp32) into AH; commit chunk-0 weights
#pragma unroll
    for (int mt = 0; mt < 2; ++mt)
#pragma unroll
        for (int t = 0; t < 8; ++t) {
            const float* a4 = acc + (mt * 8 + t) * 4;
            int r0 = mBase + mt * 16 + g;
            int c  = nBase + t * 8 + 2 * ctg;
            *reinterpret_cast<float2*>(&sAH[r0 * LDA + c]) =
                make_float2(a4[0], a4[1]);
            *reinterpret_cast<float2*>(&sAH[(r0 + 8) * LDA + c]) =
                make_float2(a4[2], a4[3]);
        }
    sts_tile<true>(rW, sW0, LDW, tid);
    __syncthreads();

    float gate[64];

    // chunk 0: r = sigmoid(ir + h@Whr); prefetch Whn
    ldg_tile(Whn, DHID, rW, tid);
#pragma unroll
    for (int i = 0; i < 64; ++i) acc[i] = 0.0f;
    gemm_tile<true>(sAH, sW0, acc, mBase, nBase, g, ctg);
    sts_tile<true>(rW, sW1, LDW, tid);   // W1 free since 2 syncs ago
    epilogue<0>(acc, gate, sAH, sX, sWi, sBi, sBhn, mBase, nBase, g, ctg);
    __syncthreads();

    // chunk 1: n = tanh(i_n + r*(h@Whn + bhn)); prefetch Whrz[:, 128:256]
    ldg_tile(Whrz + 128, 2 * DHID, rW, tid);
#pragma unroll
    for (int i = 0; i < 64; ++i) acc[i] = 0.0f;
    gemm_tile<true>(sAH, sW1, acc, mBase, nBase, g, ctg);
    sts_tile<true>(rW, sW0, LDW, tid);   // W0 free since last sync
    epilogue<1>(acc, gate, sAH, sX, sWi, sBi, sBhn, mBase, nBase, g, ctg);
    __syncthreads();

    // chunk 2: z = sigmoid(iz + h@Whz); new_h = (1-z)*n + z*h  -> AH
#pragma unroll
    for (int i = 0; i < 64; ++i) acc[i] = 0.0f;
    gemm_tile<true>(sAH, sW0, acc, mBase, nBase, g, ctg);
    epilogue<2>(acc, gate, sAH, sX, sWi, sBi, sBhn, mBase, nBase, g, ctg);
    __syncthreads();

    // coalesced writeback (x2 for the (new_h, new_h) tuple)
    float* o0 = out + rowBase * DHID;
#pragma unroll
    for (int it = 0; it < 16; ++it) {
        int i  = it * 256 + tid;
        int r  = i >> 5;
        int c4 = (i & 31) << 2;
        float4 v = *reinterpret_cast<const float4*>(sAH + r * LDA + c4);
        *reinterpret_cast<float4*>(o0 + (long)r * DHID + c4) = v;
        if (dup_off)
            *reinterpret_cast<float4*>(o0 + dup_off + (long)r * DHID + c4) = v;
    }
}

extern "C" void kernel_launch(void* const* d_in, const int* in_sizes, int n_in,
                              void* d_out, int out_size) {
    cudaFuncSetAttribute(twodrnn_kernel,
                         cudaFuncAttributeMaxDynamicSharedMemorySize,
                         SMEM_BYTES);

    const float* x    = (const float*)d_in[0];
    const float* h1   = (const float*)d_in[1];
    const float* h2   = (const float*)d_in[2];
    const float* U1   = (const float*)d_in[3];
    const float* U2   = (const float*)d_in[4];
    const float* Wi   = (const float*)d_in[5];
    const float* bi   = (const float*)d_in[6];
    const float* Whrz = (const float*)d_in[7];
    const float* Whn  = (const float*)d_in[8];
    const float* bhn  = (const float*)d_in[9];

    const int Brows = in_sizes[1] / DHID;            // 262144
    const int grid  = Brows / TILE_M;                // 2048
    const long base = (long)Brows * DHID;
    const long dup_off = ((long)out_size >= 2 * base) ? base : 0;

    twodrnn_kernel<<<grid, 256, SMEM_BYTES>>>(
        x, h1, h2, U1, U2, Wi, bi, Whrz, Whn, bhn, (float*)d_out, dup_off);
}

// round 10
// speedup vs baseline: 1.3257x; 1.3009x over previous
#include <cuda_runtime.h>
#include <cstdint>

// ---------------------------------------------------------------------------
// TwoDRNN: h = h1@U1 + h2@U2 ; GRU(h, x) -> new_h (written twice)
// B=262144, DH=128, DM=4.
// R10: TILE_M=64, 256 thr, warp tile m16xn64, 2 CTAs/SM (16 warps/SM),
//      cp.async tile loads (no register prefetch), weights pre-rounded to
//      tf32 into __device__ scratch in the padded smem image layout.
// ---------------------------------------------------------------------------

#define DHID 128
#define DMIN 4
#define TILE_M 64
#define NTHREADS 256

constexpr int LDA = 132;   // A/H tile stride (banks: 4g+ctg conflict-free)
constexpr int LDW = 136;   // W tile stride  (banks: 8ctg+g conflict-free)

constexpr int OFF_AH  = 0;
constexpr int OFF_W   = OFF_AH + TILE_M * LDA;          // 8448
constexpr int OFF_X   = OFF_W  + DHID * LDW;            // 25856
constexpr int OFF_WI  = OFF_X  + TILE_M * DMIN;         // 26112
constexpr int OFF_BI  = OFF_WI + DMIN * 3 * DHID;       // 27648
constexpr int OFF_BHN = OFF_BI + 3 * DHID;              // 28032
constexpr int SMEM_FLOATS = OFF_BHN + DHID;             // 28160
constexpr int SMEM_BYTES  = SMEM_FLOATS * 4;            // 112640 B -> 2 CTAs/SM

// Pre-rounded (tf32-rna) weight tiles, already in the 128 x LDW smem image:
// slot 0: U1, 1: U2, 2: Whrz[:,0:128], 3: Whn, 4: Whrz[:,128:256]
__device__ float g_wsc[5][DHID * LDW];

__device__ __forceinline__ unsigned f2tf(float x) {
    unsigned u;
    asm("cvt.rna.tf32.f32 %0, %1;" : "=r"(u) : "f"(x));
    return u;
}

__device__ __forceinline__ void cp16(void* s, const void* g) {
    unsigned sa = (unsigned)__cvta_generic_to_shared(s);
    asm volatile("cp.async.ca.shared.global [%0], [%1], 16;" :: "r"(sa), "l"(g));
}
__device__ __forceinline__ void cp_commit() {
    asm volatile("cp.async.commit_group;");
}
__device__ __forceinline__ void cp_wait0() {
    asm volatile("cp.async.wait_group 0;" ::: "memory");
}

__device__ __forceinline__ void mma8(float* d, unsigned a0, unsigned a1,
                                     unsigned a2, unsigned a3,
                                     unsigned b0, unsigned b1) {
    asm volatile(
        "mma.sync.aligned.m16n8k8.row.col.f32.tf32.tf32.f32 "
        "{%0,%1,%2,%3}, {%4,%5,%6,%7}, {%8,%9}, {%0,%1,%2,%3};"
        : "+f"(d[0]), "+f"(d[1]), "+f"(d[2]), "+f"(d[3])
        : "r"(a0), "r"(a1), "r"(a2), "r"(a3), "r"(b0), "r"(b1));
}

__device__ __forceinline__ float sigmoidf_(float v) {
    return 1.0f / (1.0f + __expf(-v));
}
__device__ __forceinline__ float tanhf_(float v) {
    float c = fminf(fmaxf(v, -15.0f), 15.0f);
    float e = __expf(2.0f * c);
    return (e - 1.0f) / (e + 1.0f);
}

// cp.async a 64x128 fp32 tile (row stride 128 in gmem) into sAH (stride LDA).
__device__ __forceinline__ void cp_h_tile(const float* __restrict__ g,
                                          float* sAH, int tid) {
#pragma unroll
    for (int it = 0; it < 8; ++it) {
        int i  = it * NTHREADS + tid;   // 0..2047 float4 slots
        int r  = i >> 5;
        int c4 = (i & 31) << 2;
        cp16(sAH + r * LDA + c4, g + (long)r * DHID + c4);
    }
}

// cp.async a pre-imaged weight tile (contiguous 128*LDW floats).
__device__ __forceinline__ void cp_w_tile(const float* __restrict__ g,
                                          float* sW, int tid) {
#pragma unroll
    for (int it = 0; it < 17; ++it) {
        int i = it * NTHREADS + tid;    // 0..4351 float4 slots
        cp16(sW + i * 4, g + i * 4);
    }
}

// acc += A[mBase:+16, :128] @ W[:, nBase:+64]; A rounded to tf32 in-loop.
__device__ __forceinline__ void gemm_tile(const float* sAop, const float* sWop,
                                          float acc[32], int mBase, int nBase,
                                          int g, int ctg) {
#pragma unroll
    for (int ks = 0; ks < 16; ++ks) {
        const int k0 = ks * 8;
        const float* ar0 = sAop + (mBase + g) * LDA + k0;
        const float* ar1 = ar0 + 8 * LDA;
        unsigned a0 = f2tf(ar0[ctg]);
        unsigned a1 = f2tf(ar1[ctg]);
        unsigned a2 = f2tf(ar0[ctg + 4]);
        unsigned a3 = f2tf(ar1[ctg + 4]);
        const float* bk0 = sWop + (k0 + ctg) * LDW + nBase + g;
        const float* bk1 = bk0 + 4 * LDW;
#pragma unroll
        for (int t = 0; t < 8; ++t) {
            unsigned b0 = __float_as_uint(bk0[t * 8]);
            unsigned b1 = __float_as_uint(bk1[t * 8]);
            mma8(acc + t * 4, a0, a1, a2, a3, b0, b1);
        }
    }
}

// GRU epilogue for chunk CH (0: r, 1: n, 2: z + blend into sAH).
template <int CH>
__device__ __forceinline__ void epilogue(const float acc[32], float gate[32],
                                         float* sAH, const float* sX,
                                         const float* sWi, const float* sBi,
                                         const float* sBhn,
                                         int mBase, int nBase, int g, int ctg) {
    float xv[2][4];
#pragma unroll
    for (int qh = 0; qh < 2; ++qh) {
        int rr = mBase + g + qh * 8;
#pragma unroll
        for (int k = 0; k < 4; ++k) xv[qh][k] = sX[rr * 4 + k];
    }
#pragma unroll
    for (int t = 0; t < 8; ++t) {
#pragma unroll
        for (int ql = 0; ql < 2; ++ql) {
            const int cc = nBase + t * 8 + 2 * ctg + ql;
            const int j  = cc + (CH == 0 ? 0 : (CH == 1 ? 256 : 128));
            const float w0 = sWi[0 * 384 + j];
            const float w1 = sWi[1 * 384 + j];
            const float w2 = sWi[2 * 384 + j];
            const float w3 = sWi[3 * 384 + j];
            const float bb = sBi[j];
            const float bh = (CH == 1) ? sBhn[cc] : 0.0f;
#pragma unroll
            for (int qh = 0; qh < 2; ++qh) {
                const int idx = t * 4 + qh * 2 + ql;
                const float* xp = xv[qh];
                float ip = bb + xp[0] * w0 + xp[1] * w1
                              + xp[2] * w2 + xp[3] * w3;
                const float v = acc[idx];
                if (CH == 0) {
                    gate[idx] = sigmoidf_(ip + v);                  // r
                } else if (CH == 1) {
                    gate[idx] = tanhf_(ip + gate[idx] * (v + bh));  // n
                } else {
                    const int rr = mBase + g + qh * 8;
                    float z  = sigmoidf_(ip + v);
                    float hv = sAH[rr * LDA + cc];
                    sAH[rr * LDA + cc] = (1.0f - z) * gate[idx] + z * hv;
                }
            }
        }
    }
}

// Prologue: round weights to tf32 and lay them out as the smem image.
__global__ void preround_kernel(const float* __restrict__ U1,
                                const float* __restrict__ U2,
                                const float* __restrict__ Whrz,
                                const float* __restrict__ Whn) {
    const int s = blockIdx.y;       // tile slot 0..4
    const int k = blockIdx.x;       // 0..127
    const int n = threadIdx.x;      // 0..127
    float v;
    if      (s == 0) v = U1[k * 128 + n];
    else if (s == 1) v = U2[k * 128 + n];
    else if (s == 2) v = Whrz[k * 256 + n];
    else if (s == 3) v = Whn[k * 128 + n];
    else             v = Whrz[k * 256 + 128 + n];
    g_wsc[s][k * LDW + n] = __uint_as_float(f2tf(v));
}

__global__ __launch_bounds__(NTHREADS, 2)
void twodrnn_kernel(const float* __restrict__ x,
                    const float* __restrict__ h1,
                    const float* __restrict__ h2,
                    const float* __restrict__ Wi,
                    const float* __restrict__ bi,
                    const float* __restrict__ bhn,
                    float* __restrict__ out,
                    long dup_off) {
    extern __shared__ float sm[];
    float* sAH  = sm + OFF_AH;
    float* sW   = sm + OFF_W;
    float* sX   = sm + OFF_X;
    float* sWi  = sm + OFF_WI;
    float* sBi  = sm + OFF_BI;
    float* sBhn = sm + OFF_BHN;

    const int tid  = threadIdx.x;
    const int warp = tid >> 5;
    const int lane = tid & 31;
    const int g    = lane >> 2;
    const int ctg  = lane & 3;
    const int mBase = (warp & 3) * 16;   // 4 m-tiles
    const int nBase = (warp >> 2) * 64;  // 2 n-halves
    const long rowBase = (long)blockIdx.x * TILE_M;

    // phase 0: h1 + U1 + small params
    cp_h_tile(h1 + rowBase * DHID, sAH, tid);
    cp_w_tile(g_wsc[0], sW, tid);
    cp_commit();
    for (int i = tid; i < DMIN * 3 * DHID; i += NTHREADS) sWi[i] = Wi[i];
    for (int i = tid; i < 3 * DHID; i += NTHREADS)        sBi[i] = bi[i];
    for (int i = tid; i < DHID; i += NTHREADS)            sBhn[i] = bhn[i];
    for (int i = tid; i < TILE_M * DMIN; i += NTHREADS)   sX[i] = x[rowBase * DMIN + i];
    cp_wait0();
    __syncthreads();

    float acc[32];
#pragma unroll
    for (int i = 0; i < 32; ++i) acc[i] = 0.0f;

    gemm_tile(sAH, sW, acc, mBase, nBase, g, ctg);      // h1@U1
    __syncthreads();

    cp_h_tile(h2 + rowBase * DHID, sAH, tid);
    cp_w_tile(g_wsc[1], sW, tid);
    cp_commit();
    cp_wait0();
    __syncthreads();

    gemm_tile(sAH, sW, acc, mBase, nBase, g, ctg);      // += h2@U2
    __syncthreads();

    // stage h (fp32) into sAH; fetch chunk-0 weights meanwhile
    cp_w_tile(g_wsc[2], sW, tid);
    cp_commit();
#pragma unroll
    for (int t = 0; t < 8; ++t) {
        const float* a4 = acc + t * 4;
        int r0 = mBase + g;
        int c  = nBase + t * 8 + 2 * ctg;
        *reinterpret_cast<float2*>(&sAH[r0 * LDA + c]) = make_float2(a4[0], a4[1]);
        *reinterpret_cast<float2*>(&sAH[(r0 + 8) * LDA + c]) = make_float2(a4[2], a4[3]);
    }
    cp_wait0();
    __syncthreads();

    float gate[32];

    // chunk 0: r
#pragma unroll
    for (int i = 0; i < 32; ++i) acc[i] = 0.0f;
    gemm_tile(sAH, sW, acc, mBase, nBase, g, ctg);
    __syncthreads();                       // sW free
    cp_w_tile(g_wsc[3], sW, tid);
    cp_commit();
    epilogue<0>(acc, gate, sAH, sX, sWi, sBi, sBhn, mBase, nBase, g, ctg);
    cp_wait0();
    __syncthreads();

    // chunk 1: n
#pragma unroll
    for (int i = 0; i < 32; ++i) acc[i] = 0.0f;
    gemm_tile(sAH, sW, acc, mBase, nBase, g, ctg);
    __syncthreads();
    cp_w_tile(g_wsc[4], sW, tid);
    cp_commit();
    epilogue<1>(acc, gate, sAH, sX, sWi, sBi, sBhn, mBase, nBase, g, ctg);
    cp_wait0();
    __syncthreads();

    // chunk 2: z + blend (epilogue writes sAH -> sync after gemm first)
#pragma unroll
    for (int i = 0; i < 32; ++i) acc[i] = 0.0f;
    gemm_tile(sAH, sW, acc, mBase, nBase, g, ctg);
    __syncthreads();                       // all gemm reads of sAH done
    epilogue<2>(acc, gate, sAH, sX, sWi, sBi, sBhn, mBase, nBase, g, ctg);
    __syncthreads();

    // coalesced writeback (x2 for the (new_h, new_h) tuple)
    float* o0 = out + rowBase * DHID;
#pragma unroll
    for (int it = 0; it < 8; ++it) {
        int i  = it * NTHREADS + tid;
        int r  = i >> 5;
        int c4 = (i & 31) << 2;
        float4 v = *reinterpret_cast<const float4*>(sAH + r * LDA + c4);
        *reinterpret_cast<float4*>(o0 + (long)r * DHID + c4) = v;
        if (dup_off)
            *reinterpret_cast<float4*>(o0 + dup_off + (long)r * DHID + c4) = v;
    }
}

extern "C" void kernel_launch(void* const* d_in, const int* in_sizes, int n_in,
                              void* d_out, int out_size) {
    cudaFuncSetAttribute(twodrnn_kernel,
                         cudaFuncAttributeMaxDynamicSharedMemorySize,
                         SMEM_BYTES);

    const float* x    = (const float*)d_in[0];
    const float* h1   = (const float*)d_in[1];
    const float* h2   = (const float*)d_in[2];
    const float* U1   = (const float*)d_in[3];
    const float* U2   = (const float*)d_in[4];
    const float* Wi   = (const float*)d_in[5];
    const float* bi   = (const float*)d_in[6];
    const float* Whrz = (const float*)d_in[7];
    const float* Whn  = (const float*)d_in[8];
    const float* bhn  = (const float*)d_in[9];

    const int Brows = in_sizes[1] / DHID;            // 262144
    const int grid  = Brows / TILE_M;                // 4096
    const long base = (long)Brows * DHID;
    const long dup_off = ((long)out_size >= 2 * base) ? base : 0;

    preround_kernel<<<dim3(DHID, 5), DHID>>>(U1, U2, Whrz, Whn);
    twodrnn_kernel<<<grid, NTHREADS, SMEM_BYTES>>>(
        x, h1, h2, Wi, bi, bhn, (float*)d_out, dup_off);
}